// round 4
// baseline (speedup 1.0000x reference)
#include <cuda_runtime.h>

// ---------------------------------------------------------------------------
// G1_sub2_and_sub3_update
//
// Stage A (sub2): out[rc[c]] = emb[rc[c]] + sum_{e: col==c} emb[ls[s2row[e]]]
//                              + (n_ent - deg2[c])
// Stage B (sub3): msg[c] = sum_{e: col==c} out[lc[s3row[e]]]   (updated type rows)
//                 out[rs[c]] = emb[rs[c]] * (1 - (msg[c] + (n_typ - deg3[c])) / (1 + deg3[c]))
//
// Stage B caches the (tiny) updated type table in shared memory, split into
// 4 dim-slices of 32 floats (128 KB per CTA), removing all L2 gather traffic
// and the lc indirection from the hot loop. Edge lists are sorted by column;
// uniform-degree fast path with O(1) validation, binary-search fallback.
// ---------------------------------------------------------------------------

#define EMB_D   128
#define SLICE_D 32
#define NSLICE  4
#define NGROUPS 37          // 37 * 4 = 148 CTAs = one full wave

static __device__ __forceinline__ int lower_bound_i(const int* __restrict__ a, int n, int v) {
    int lo = 0, hi = n;
    while (lo < hi) {
        int m = (lo + hi) >> 1;
        if (__ldg(a + m) < v) lo = m + 1; else hi = m;
    }
    return lo;
}

static __device__ __forceinline__ void seg_bounds(const int* __restrict__ col, int E,
                                                  int c, int degGuess,
                                                  int& lo, int& hi) {
    lo = c * degGuess;
    hi = lo + degGuess;
    bool ok = (hi <= E)
           && (__ldg(col + lo) == c)
           && (__ldg(col + hi - 1) == c)
           && (lo == 0 || __ldg(col + lo - 1) != c)
           && (hi == E || __ldg(col + hi) != c);
    if (!ok) {
        lo = lower_bound_i(col, E, c);
        hi = lower_bound_i(col, E, c + 1);
    }
}

// ---------------- Stage A: one block (512 thr = 4 edge-groups x 128 dims) --
__global__ __launch_bounds__(512)
void k_type_update(const float* __restrict__ emb,
                   const int* __restrict__ s2row,
                   const int* __restrict__ s2col, int E2, int degGuess2,
                   const int* __restrict__ ls,
                   const int* __restrict__ rc,
                   float n_ent_f,
                   float* __restrict__ out) {
    __shared__ float red[512];
    const int c   = blockIdx.x;
    const int tid = threadIdx.x;
    const int d   = tid & 127;     // dim
    const int g   = tid >> 7;      // edge group 0..3

    int lo, hi;
    seg_bounds(s2col, E2, c, degGuess2, lo, hi);
    const int deg = hi - lo;

    float acc = 0.f;
    int e = lo + g;
    // strided by 4 groups, unrolled x4 -> up to 16 rows in flight per CTA
    for (; e + 12 < hi; e += 16) {
        int r0 = __ldg(s2row + e + 0);
        int r1 = __ldg(s2row + e + 4);
        int r2 = __ldg(s2row + e + 8);
        int r3 = __ldg(s2row + e + 12);
        int s0 = __ldg(ls + r0);
        int s1 = __ldg(ls + r1);
        int s2 = __ldg(ls + r2);
        int s3 = __ldg(ls + r3);
        float v0 = __ldg(emb + (size_t)s0 * EMB_D + d);
        float v1 = __ldg(emb + (size_t)s1 * EMB_D + d);
        float v2 = __ldg(emb + (size_t)s2 * EMB_D + d);
        float v3 = __ldg(emb + (size_t)s3 * EMB_D + d);
        acc += (v0 + v1) + (v2 + v3);
    }
    for (; e < hi; e += 4) {
        int r = __ldg(s2row + e);
        int s = __ldg(ls + r);
        acc += __ldg(emb + (size_t)s * EMB_D + d);
    }

    red[tid] = acc;
    __syncthreads();
    if (g == 0) {
        float total = red[d] + red[128 + d] + red[256 + d] + red[384 + d];
        const int node = __ldg(rc + c);
        const float base = __ldg(emb + (size_t)node * EMB_D + d);
        out[(size_t)node * EMB_D + d] = base + total + (n_ent_f - (float)deg);
    }
}

// ---------------- Stage B (smem table): 148 CTAs, 1024 thr, persistent ----
extern __shared__ char sb_smem[];

__global__ __launch_bounds__(1024, 1)
void k_entity_smem(const float* __restrict__ emb,
                   const int* __restrict__ s3row,
                   const int* __restrict__ s3col, int E3, int degGuess3,
                   const int* __restrict__ lc,
                   const int* __restrict__ rs,
                   int n_ent, float n_typ_f, int n_typ,
                   float* __restrict__ out) {
    float* table = (float*)sb_smem;                    // [n_typ][SLICE_D]
    int*   lcbuf = (int*)(table + (size_t)n_typ * SLICE_D);

    const int slice = blockIdx.x % NSLICE;
    const int group = blockIdx.x / NSLICE;
    const int tid   = threadIdx.x;
    const int doff  = slice * SLICE_D;

    // Stage the lc map, then the type-row slice table (gathered from out,
    // which stage A has already updated).
    for (int r = tid; r < n_typ; r += blockDim.x) lcbuf[r] = __ldg(lc + r);
    __syncthreads();
    for (int idx = tid; idx < n_typ * SLICE_D; idx += blockDim.x) {
        int r = idx / SLICE_D, dd = idx % SLICE_D;
        table[idx] = out[(size_t)lcbuf[r] * EMB_D + doff + dd];
    }
    __syncthreads();

    const int per = (n_ent + NGROUPS - 1) / NGROUPS;
    const int n0  = group * per;
    const int n1  = (n0 + per < n_ent) ? (n0 + per) : n_ent;

    const int warp   = tid >> 5;
    const int lane   = tid & 31;
    const int nwarps = blockDim.x >> 5;

    int c = n0 + warp;
    // 2-node software pipeline: both nodes' loads issued before either is used.
    for (; c + nwarps < n1; c += 2 * nwarps) {
        const int cB = c + nwarps;

        int loA, hiA, loB, hiB;
        seg_bounds(s3col, E3, c,  degGuess3, loA, hiA);
        seg_bounds(s3col, E3, cB, degGuess3, loB, hiB);
        const int nodeA = __ldg(rs + c);
        const int nodeB = __ldg(rs + cB);
        const float evA = __ldg(emb + (size_t)nodeA * EMB_D + doff + lane);
        const float evB = __ldg(emb + (size_t)nodeB * EMB_D + doff + lane);

        const int degA = hiA - loA, degB = hiB - loB;
        float msgA = n_typ_f - (float)degA;
        float msgB = n_typ_f - (float)degB;

        if (degA == 4 && degB == 4) {
            int a0 = __ldg(s3row + loA + 0), a1 = __ldg(s3row + loA + 1);
            int a2 = __ldg(s3row + loA + 2), a3 = __ldg(s3row + loA + 3);
            int b0 = __ldg(s3row + loB + 0), b1 = __ldg(s3row + loB + 1);
            int b2 = __ldg(s3row + loB + 2), b3 = __ldg(s3row + loB + 3);
            msgA += (table[a0 * SLICE_D + lane] + table[a1 * SLICE_D + lane])
                  + (table[a2 * SLICE_D + lane] + table[a3 * SLICE_D + lane]);
            msgB += (table[b0 * SLICE_D + lane] + table[b1 * SLICE_D + lane])
                  + (table[b2 * SLICE_D + lane] + table[b3 * SLICE_D + lane]);
        } else {
            for (int e = loA; e < hiA; ++e) msgA += table[__ldg(s3row + e) * SLICE_D + lane];
            for (int e = loB; e < hiB; ++e) msgB += table[__ldg(s3row + e) * SLICE_D + lane];
        }

        const float invA = 1.f / (1.f + (float)degA);
        const float invB = 1.f / (1.f + (float)degB);
        out[(size_t)nodeA * EMB_D + doff + lane] = evA * (1.f - msgA * invA);
        out[(size_t)nodeB * EMB_D + doff + lane] = evB * (1.f - msgB * invB);
    }
    for (; c < n1; c += nwarps) {
        int lo, hi;
        seg_bounds(s3col, E3, c, degGuess3, lo, hi);
        const int deg = hi - lo;
        const int node = __ldg(rs + c);
        const float ev = __ldg(emb + (size_t)node * EMB_D + doff + lane);
        float msg = n_typ_f - (float)deg;
        for (int e = lo; e < hi; ++e) msg += table[__ldg(s3row + e) * SLICE_D + lane];
        out[(size_t)node * EMB_D + doff + lane] = ev * (1.f - msg * (1.f / (1.f + (float)deg)));
    }
}

// ---------------- Fallback stage B (warp per node, no smem table) ---------
__global__ void k_entity_update(const float* __restrict__ emb,
                                const int* __restrict__ s3row,
                                const int* __restrict__ s3col, int E3, int degGuess3,
                                const int* __restrict__ lc,
                                const int* __restrict__ rs,
                                int n_ent, float n_typ_f,
                                float* out) {
    const int c    = (int)((blockIdx.x * (unsigned)blockDim.x + threadIdx.x) >> 5);
    const int lane = threadIdx.x & 31;
    if (c >= n_ent) return;

    int lo, hi;
    seg_bounds(s3col, E3, c, degGuess3, lo, hi);
    const int deg = hi - lo;
    const float inv  = 1.f / (1.f + (float)deg);
    const float bias = n_typ_f - (float)deg;

    const int node = __ldg(rs + c);
    const float4 e4 = __ldg((const float4*)(emb + (size_t)node * EMB_D) + lane);

    float4 msg = make_float4(bias, bias, bias, bias);
    for (int e = lo; e < hi; ++e) {
        int r = __ldg(s3row + e);
        int t = __ldg(lc + r);
        float4 v = *((const float4*)(out + (size_t)t * EMB_D) + lane);
        msg.x += v.x; msg.y += v.y; msg.z += v.z; msg.w += v.w;
    }
    float4 res;
    res.x = e4.x * (1.f - msg.x * inv);
    res.y = e4.y * (1.f - msg.y * inv);
    res.z = e4.z * (1.f - msg.z * inv);
    res.w = e4.w * (1.f - msg.w * inv);
    *((float4*)(out + (size_t)node * EMB_D) + lane) = res;
}

extern "C" void kernel_launch(void* const* d_in, const int* in_sizes, int n_in,
                              void* d_out, int out_size) {
    const float* emb  = (const float*)d_in[0];
    const int* s2row  = (const int*)d_in[1];
    const int* s2col  = (const int*)d_in[2];
    const int* s3row  = (const int*)d_in[3];
    const int* s3col  = (const int*)d_in[4];
    const int* ls     = (const int*)d_in[5];
    const int* rc     = (const int*)d_in[6];
    const int* lc     = (const int*)d_in[7];
    const int* rs     = (const int*)d_in[8];

    const int E2    = in_sizes[1];
    const int E3    = in_sizes[3];
    const int n_ent = in_sizes[5];
    const int n_typ = in_sizes[6];

    const int degGuess2 = (n_typ > 0) ? (E2 / n_typ) : 1;
    const int degGuess3 = (n_ent > 0) ? (E3 / n_ent) : 1;

    float* out = (float*)d_out;

    // Stage A
    k_type_update<<<n_typ, 512>>>(emb, s2row, s2col, E2, degGuess2, ls, rc,
                                  (float)n_ent, out);

    // Stage B
    size_t smem_bytes = (size_t)n_typ * SLICE_D * sizeof(float)
                      + (size_t)n_typ * sizeof(int);
    if (smem_bytes <= 180 * 1024) {
        cudaFuncSetAttribute(k_entity_smem,
                             cudaFuncAttributeMaxDynamicSharedMemorySize,
                             (int)smem_bytes);
        k_entity_smem<<<NGROUPS * NSLICE, 1024, smem_bytes>>>(
            emb, s3row, s3col, E3, degGuess3, lc, rs,
            n_ent, (float)n_typ, n_typ, out);
    } else {
        const int threads = 256;
        const int blocks = (n_ent + (threads / 32) - 1) / (threads / 32);
        k_entity_update<<<blocks, threads>>>(emb, s3row, s3col, E3, degGuess3,
                                             lc, rs, n_ent, (float)n_typ, out);
    }
}

// round 7
// speedup vs baseline: 2.5971x; 2.5971x over previous
#include <cuda_runtime.h>

// ---------------------------------------------------------------------------
// G1_sub2_and_sub3_update
//
// Stage A (sub2): out[rc[c]] = emb[rc[c]] + sum_{e: col==c} emb[ls[s2row[e]]]
//                              + (n_ent - deg2[c])
// Stage B (sub3): msg[c] = sum_{e: col==c} out[lc[s3row[e]]]   (updated type rows)
//                 out[rs[c]] = emb[rs[c]] * (1 - (msg[c] + (n_typ - deg3[c])) / (1 + deg3[c]))
//
// Edge lists are sorted by column. Uniform-degree fast path (O(1) validated),
// binary-search fallback. Stage B: one warp per 2 adjacent nodes to double
// memory-level parallelism. No atomics, no scratch memory.
// ---------------------------------------------------------------------------

#define EMB_D 128

static __device__ __forceinline__ int lower_bound_i(const int* __restrict__ a, int n, int v) {
    int lo = 0, hi = n;
    while (lo < hi) {
        int m = (lo + hi) >> 1;
        if (__ldg(a + m) < v) lo = m + 1; else hi = m;
    }
    return lo;
}

static __device__ __forceinline__ void seg_bounds(const int* __restrict__ col, int E,
                                                  int c, int degGuess,
                                                  int& lo, int& hi) {
    lo = c * degGuess;
    hi = lo + degGuess;
    bool ok = (hi <= E)
           && (__ldg(col + lo) == c)
           && (__ldg(col + hi - 1) == c)
           && (lo == 0 || __ldg(col + lo - 1) != c)
           && (hi == E || __ldg(col + hi) != c);
    if (!ok) {
        lo = lower_bound_i(col, E, c);
        hi = lower_bound_i(col, E, c + 1);
    }
}

// ---------------- Stage A: one block (512 thr = 4 edge-groups x 128 dims) --
__global__ __launch_bounds__(512)
void k_type_update(const float* __restrict__ emb,
                   const int* __restrict__ s2row,
                   const int* __restrict__ s2col, int E2, int degGuess2,
                   const int* __restrict__ ls,
                   const int* __restrict__ rc,
                   float n_ent_f,
                   float* __restrict__ out) {
    __shared__ float red[512];
    const int c   = blockIdx.x;
    const int tid = threadIdx.x;
    const int d   = tid & 127;     // dim
    const int g   = tid >> 7;      // edge group 0..3

    int lo, hi;
    seg_bounds(s2col, E2, c, degGuess2, lo, hi);
    const int deg = hi - lo;

    float acc = 0.f;
    if (deg == 64) {
        // Fast path: 16 contiguous edges per group, all loads batched.
        const int base = lo + g * 16;
        int rr[16];
#pragma unroll
        for (int i = 0; i < 16; ++i) rr[i] = __ldg(s2row + base + i);
#pragma unroll
        for (int i = 0; i < 16; ++i) rr[i] = __ldg(ls + rr[i]);
        float v[16];
#pragma unroll
        for (int i = 0; i < 16; ++i) v[i] = __ldg(emb + (size_t)rr[i] * EMB_D + d);
#pragma unroll
        for (int i = 0; i < 16; ++i) acc += v[i];
    } else {
        for (int e = lo + g; e < hi; e += 4) {
            int r = __ldg(s2row + e);
            int s = __ldg(ls + r);
            acc += __ldg(emb + (size_t)s * EMB_D + d);
        }
    }

    red[tid] = acc;
    __syncthreads();
    if (g == 0) {
        float total = red[d] + red[128 + d] + red[256 + d] + red[384 + d];
        const int node = __ldg(rc + c);
        const float base = __ldg(emb + (size_t)node * EMB_D + d);
        out[(size_t)node * EMB_D + d] = base + total + (n_ent_f - (float)deg);
    }
}

// ---------------- Stage B: one warp per TWO adjacent entity nodes ---------
__global__ __launch_bounds__(256, 4)
void k_entity_update(const float* __restrict__ emb,
                     const int* __restrict__ s3row,
                     const int* __restrict__ s3col, int E3, int degGuess3,
                     const int* __restrict__ lc,
                     const int* __restrict__ rs,
                     int n_ent, float n_typ_f,
                     float* out) {
    const int w    = (int)((blockIdx.x * (unsigned)blockDim.x + threadIdx.x) >> 5);
    const int lane = threadIdx.x & 31;
    const int c0   = 2 * w;            // adjacent pair -> shared cache lines
    const int c1   = c0 + 1;
    if (c0 >= n_ent) return;
    const bool hasB = (c1 < n_ent);

    int loA, hiA, loB = 0, hiB = 0;
    seg_bounds(s3col, E3, c0, degGuess3, loA, hiA);
    if (hasB) seg_bounds(s3col, E3, c1, degGuess3, loB, hiB);
    const int degA = hiA - loA;
    const int degB = hiB - loB;

    // Entity rows: two adjacent 512 B rows -> 1 KB contiguous stream.
    const int nodeA = __ldg(rs + c0);
    const int nodeB = hasB ? __ldg(rs + c1) : nodeA;
    const float4 eA = __ldg((const float4*)(emb + (size_t)nodeA * EMB_D) + lane);
    const float4 eB = __ldg((const float4*)(emb + (size_t)nodeB * EMB_D) + lane);

    const float biasA = n_typ_f - (float)degA;
    const float biasB = n_typ_f - (float)degB;
    float4 mA = make_float4(biasA, biasA, biasA, biasA);
    float4 mB = make_float4(biasB, biasB, biasB, biasB);

    if (degA == 4 && degB == 4) {
        // Hot path: 8 independent type-row gathers in flight.
        int a0 = __ldg(s3row + loA + 0), a1 = __ldg(s3row + loA + 1);
        int a2 = __ldg(s3row + loA + 2), a3 = __ldg(s3row + loA + 3);
        int b0 = __ldg(s3row + loB + 0), b1 = __ldg(s3row + loB + 1);
        int b2 = __ldg(s3row + loB + 2), b3 = __ldg(s3row + loB + 3);
        a0 = __ldg(lc + a0); a1 = __ldg(lc + a1);
        a2 = __ldg(lc + a2); a3 = __ldg(lc + a3);
        b0 = __ldg(lc + b0); b1 = __ldg(lc + b1);
        b2 = __ldg(lc + b2); b3 = __ldg(lc + b3);
        const float4 vA0 = *((const float4*)(out + (size_t)a0 * EMB_D) + lane);
        const float4 vA1 = *((const float4*)(out + (size_t)a1 * EMB_D) + lane);
        const float4 vA2 = *((const float4*)(out + (size_t)a2 * EMB_D) + lane);
        const float4 vA3 = *((const float4*)(out + (size_t)a3 * EMB_D) + lane);
        const float4 vB0 = *((const float4*)(out + (size_t)b0 * EMB_D) + lane);
        const float4 vB1 = *((const float4*)(out + (size_t)b1 * EMB_D) + lane);
        const float4 vB2 = *((const float4*)(out + (size_t)b2 * EMB_D) + lane);
        const float4 vB3 = *((const float4*)(out + (size_t)b3 * EMB_D) + lane);
        mA.x += (vA0.x + vA1.x) + (vA2.x + vA3.x);
        mA.y += (vA0.y + vA1.y) + (vA2.y + vA3.y);
        mA.z += (vA0.z + vA1.z) + (vA2.z + vA3.z);
        mA.w += (vA0.w + vA1.w) + (vA2.w + vA3.w);
        mB.x += (vB0.x + vB1.x) + (vB2.x + vB3.x);
        mB.y += (vB0.y + vB1.y) + (vB2.y + vB3.y);
        mB.z += (vB0.z + vB1.z) + (vB2.z + vB3.z);
        mB.w += (vB0.w + vB1.w) + (vB2.w + vB3.w);
    } else {
        for (int e = loA; e < hiA; ++e) {
            int t = __ldg(lc + __ldg(s3row + e));
            float4 v = *((const float4*)(out + (size_t)t * EMB_D) + lane);
            mA.x += v.x; mA.y += v.y; mA.z += v.z; mA.w += v.w;
        }
        for (int e = loB; e < hiB; ++e) {
            int t = __ldg(lc + __ldg(s3row + e));
            float4 v = *((const float4*)(out + (size_t)t * EMB_D) + lane);
            mB.x += v.x; mB.y += v.y; mB.z += v.z; mB.w += v.w;
        }
    }

    const float invA = 1.f / (1.f + (float)degA);
    float4 rA;
    rA.x = eA.x * (1.f - mA.x * invA);
    rA.y = eA.y * (1.f - mA.y * invA);
    rA.z = eA.z * (1.f - mA.z * invA);
    rA.w = eA.w * (1.f - mA.w * invA);
    *((float4*)(out + (size_t)nodeA * EMB_D) + lane) = rA;

    if (hasB) {
        const float invB = 1.f / (1.f + (float)degB);
        float4 rB;
        rB.x = eB.x * (1.f - mB.x * invB);
        rB.y = eB.y * (1.f - mB.y * invB);
        rB.z = eB.z * (1.f - mB.z * invB);
        rB.w = eB.w * (1.f - mB.w * invB);
        *((float4*)(out + (size_t)nodeB * EMB_D) + lane) = rB;
    }
}

extern "C" void kernel_launch(void* const* d_in, const int* in_sizes, int n_in,
                              void* d_out, int out_size) {
    const float* emb  = (const float*)d_in[0];
    const int* s2row  = (const int*)d_in[1];
    const int* s2col  = (const int*)d_in[2];
    const int* s3row  = (const int*)d_in[3];
    const int* s3col  = (const int*)d_in[4];
    const int* ls     = (const int*)d_in[5];
    const int* rc     = (const int*)d_in[6];
    const int* lc     = (const int*)d_in[7];
    const int* rs     = (const int*)d_in[8];

    const int E2    = in_sizes[1];
    const int E3    = in_sizes[3];
    const int n_ent = in_sizes[5];
    const int n_typ = in_sizes[6];

    const int degGuess2 = (n_typ > 0) ? (E2 / n_typ) : 1;
    const int degGuess3 = (n_ent > 0) ? (E3 / n_ent) : 1;

    float* out = (float*)d_out;

    // Stage A: update type rows into out.
    k_type_update<<<n_typ, 512>>>(emb, s2row, s2col, E2, degGuess2, ls, rc,
                                  (float)n_ent, out);

    // Stage B: one warp per two adjacent entity nodes.
    const int threads = 256;
    const int nodes_per_cta = (threads / 32) * 2;    // 16
    const int blocks = (n_ent + nodes_per_cta - 1) / nodes_per_cta;
    k_entity_update<<<blocks, threads>>>(emb, s3row, s3col, E3, degGuess3,
                                         lc, rs, n_ent, (float)n_typ, out);
}

// round 10
// speedup vs baseline: 3.7243x; 1.4340x over previous
#include <cuda_runtime.h>

// ---------------------------------------------------------------------------
// G1_sub2_and_sub3_update
//
// Stage A (sub2): out[rc[c]] = emb[rc[c]] + sum_{e: col==c} emb[ls[s2row[e]]]
//                              + (n_ent - deg2[c])
// Stage B (sub3): msg[c] = sum_{e: col==c} out[lc[s3row[e]]]   (updated type rows)
//                 out[rs[c]] = emb[rs[c]] * (1 - (msg[c] + (n_typ - deg3[c])) / (1 + deg3[c]))
//
// Stage B is tiled 64 nodes / 256 edges per CTA. Each thread stages one edge's
// type id through shared memory (coalesced) while validating uniform degree 4
// (col[e] == e/4, plus two boundary probes); a single __syncthreads_and is
// both the validation reduce and the staging barrier. Hot loop: warp = 8
// nodes, processed in pairs, only gathers + math. Generic fallback otherwise.
// All shared accesses are scalar (no wide LDS).
// ---------------------------------------------------------------------------

#define EMB_D 128
#define TILE  64

static __device__ __forceinline__ int lower_bound_i(const int* __restrict__ a, int n, int v) {
    int lo = 0, hi = n;
    while (lo < hi) {
        int m = (lo + hi) >> 1;
        if (__ldg(a + m) < v) lo = m + 1; else hi = m;
    }
    return lo;
}

static __device__ __forceinline__ void seg_bounds(const int* __restrict__ col, int E,
                                                  int c, int degGuess,
                                                  int& lo, int& hi) {
    lo = c * degGuess;
    hi = lo + degGuess;
    bool ok = (hi <= E)
           && (__ldg(col + lo) == c)
           && (__ldg(col + hi - 1) == c)
           && (lo == 0 || __ldg(col + lo - 1) != c)
           && (hi == E || __ldg(col + hi) != c);
    if (!ok) {
        lo = lower_bound_i(col, E, c);
        hi = lower_bound_i(col, E, c + 1);
    }
}

// ---------------- Stage A: one block (512 thr = 4 edge-groups x 128 dims) --
__global__ __launch_bounds__(512)
void k_type_update(const float* __restrict__ emb,
                   const int* __restrict__ s2row,
                   const int* __restrict__ s2col, int E2, int degGuess2,
                   const int* __restrict__ ls,
                   const int* __restrict__ rc,
                   float n_ent_f,
                   float* __restrict__ out) {
    __shared__ float red[512];
    const int c   = blockIdx.x;
    const int tid = threadIdx.x;
    const int d   = tid & 127;     // dim
    const int g   = tid >> 7;      // edge group 0..3

    int lo, hi;
    seg_bounds(s2col, E2, c, degGuess2, lo, hi);
    const int deg = hi - lo;

    float acc = 0.f;
    if (deg == 64) {
        const int base = lo + g * 16;
        int rr[16];
#pragma unroll
        for (int i = 0; i < 16; ++i) rr[i] = __ldg(s2row + base + i);
#pragma unroll
        for (int i = 0; i < 16; ++i) rr[i] = __ldg(ls + rr[i]);
        float v[16];
#pragma unroll
        for (int i = 0; i < 16; ++i) v[i] = __ldg(emb + (size_t)rr[i] * EMB_D + d);
#pragma unroll
        for (int i = 0; i < 16; ++i) acc += v[i];
    } else {
        for (int e = lo + g; e < hi; e += 4) {
            int r = __ldg(s2row + e);
            int s = __ldg(ls + r);
            acc += __ldg(emb + (size_t)s * EMB_D + d);
        }
    }

    red[tid] = acc;
    __syncthreads();
    if (g == 0) {
        float total = red[d] + red[128 + d] + red[256 + d] + red[384 + d];
        const int node = __ldg(rc + c);
        const float base = __ldg(emb + (size_t)node * EMB_D + d);
        out[(size_t)node * EMB_D + d] = base + total + (n_ent_f - (float)deg);
    }
}

// ---------------- Stage B: 64-node tiles, smem-staged indices --------------
__global__ __launch_bounds__(256, 4)
void k_entity_tiled(const float* __restrict__ emb,
                    const int* __restrict__ s3row,
                    const int* __restrict__ s3col, int E3, int degGuess3,
                    const int* __restrict__ lc,
                    const int* __restrict__ rs,
                    int n_ent, float n_typ_f,
                    float* out) {
    __shared__ __align__(16) int s_t[TILE * 4];   // type id per edge of tile
    __shared__ __align__(16) int s_rs[TILE];      // output node id per node

    const int t      = threadIdx.x;
    const int c_base = blockIdx.x * TILE;
    const int nloc   = min(TILE, n_ent - c_base);

    // Fast path is possible only if the global edge list could be uniform deg-4.
    const bool tile_full = (degGuess3 == 4) && (nloc == TILE) && (4 * n_ent <= E3);

    bool ok = tile_full;
    if (tile_full) {
        const int e = 4 * c_base + t;              // this tile's 256 edges
        // Stage (coalesced) and validate the same edge.
        const int col_e = __ldg(s3col + e);
        s_t[t] = __ldg(lc + __ldg(s3row + e));
        ok = (col_e == (e >> 2));
        if (t < TILE) s_rs[t] = __ldg(rs + c_base + t);
        // Boundary probes (sortedness makes these sufficient).
        if (t == 0) {
            ok = ok && ((c_base == 0) || (__ldg(s3col + 4 * c_base - 1) < c_base));
        } else if (t == 1) {
            const int endi = 4 * (c_base + TILE);
            ok = ok && ((endi >= E3) || (__ldg(s3col + endi) >= c_base + TILE));
        }
    }
    const int allok = __syncthreads_and(ok ? 1 : 0);   // barrier + reduce

    const int w    = t >> 5;
    const int lane = t & 31;

    if (allok) {
        const float bias = n_typ_f - 4.f;
        const float inv  = 0.2f;                       // 1/(1+4)

        // warp w handles local nodes [w*8, w*8+8), two at a time
#pragma unroll
        for (int k = 0; k < 4; ++k) {
            const int mA = w * 8 + 2 * k;
            const int mB = mA + 1;
            const int a0 = s_t[mA * 4 + 0], a1 = s_t[mA * 4 + 1];
            const int a2 = s_t[mA * 4 + 2], a3 = s_t[mA * 4 + 3];
            const int b0 = s_t[mB * 4 + 0], b1 = s_t[mB * 4 + 1];
            const int b2 = s_t[mB * 4 + 2], b3 = s_t[mB * 4 + 3];
            const int nodeA = s_rs[mA];
            const int nodeB = s_rs[mB];

            const float4 eA = __ldg((const float4*)(emb + (size_t)nodeA * EMB_D) + lane);
            const float4 eB = __ldg((const float4*)(emb + (size_t)nodeB * EMB_D) + lane);

            const float4 vA0 = __ldg((const float4*)(out + (size_t)a0 * EMB_D) + lane);
            const float4 vA1 = __ldg((const float4*)(out + (size_t)a1 * EMB_D) + lane);
            const float4 vA2 = __ldg((const float4*)(out + (size_t)a2 * EMB_D) + lane);
            const float4 vA3 = __ldg((const float4*)(out + (size_t)a3 * EMB_D) + lane);
            const float4 vB0 = __ldg((const float4*)(out + (size_t)b0 * EMB_D) + lane);
            const float4 vB1 = __ldg((const float4*)(out + (size_t)b1 * EMB_D) + lane);
            const float4 vB2 = __ldg((const float4*)(out + (size_t)b2 * EMB_D) + lane);
            const float4 vB3 = __ldg((const float4*)(out + (size_t)b3 * EMB_D) + lane);

            float4 mAcc, mBcc;
            mAcc.x = bias + (vA0.x + vA1.x) + (vA2.x + vA3.x);
            mAcc.y = bias + (vA0.y + vA1.y) + (vA2.y + vA3.y);
            mAcc.z = bias + (vA0.z + vA1.z) + (vA2.z + vA3.z);
            mAcc.w = bias + (vA0.w + vA1.w) + (vA2.w + vA3.w);
            mBcc.x = bias + (vB0.x + vB1.x) + (vB2.x + vB3.x);
            mBcc.y = bias + (vB0.y + vB1.y) + (vB2.y + vB3.y);
            mBcc.z = bias + (vB0.z + vB1.z) + (vB2.z + vB3.z);
            mBcc.w = bias + (vB0.w + vB1.w) + (vB2.w + vB3.w);

            float4 rA, rB;
            rA.x = eA.x * (1.f - mAcc.x * inv);
            rA.y = eA.y * (1.f - mAcc.y * inv);
            rA.z = eA.z * (1.f - mAcc.z * inv);
            rA.w = eA.w * (1.f - mAcc.w * inv);
            rB.x = eB.x * (1.f - mBcc.x * inv);
            rB.y = eB.y * (1.f - mBcc.y * inv);
            rB.z = eB.z * (1.f - mBcc.z * inv);
            rB.w = eB.w * (1.f - mBcc.w * inv);

            *((float4*)(out + (size_t)nodeA * EMB_D) + lane) = rA;
            *((float4*)(out + (size_t)nodeB * EMB_D) + lane) = rB;
        }
    } else {
        // ---- Generic fallback: warp per node, exact bounds ----
        for (int k = 0; k < 8; ++k) {
            const int m = w * 8 + k;
            if (m >= nloc) break;
            const int c = c_base + m;

            int lo, hi;
            seg_bounds(s3col, E3, c, degGuess3, lo, hi);
            const int deg = hi - lo;
            const float inv  = 1.f / (1.f + (float)deg);
            const float bias = n_typ_f - (float)deg;

            const int node = __ldg(rs + c);
            const float4 e4 = __ldg((const float4*)(emb + (size_t)node * EMB_D) + lane);

            float4 msg = make_float4(bias, bias, bias, bias);
            for (int e = lo; e < hi; ++e) {
                const int tt = __ldg(lc + __ldg(s3row + e));
                const float4 v = __ldg((const float4*)(out + (size_t)tt * EMB_D) + lane);
                msg.x += v.x; msg.y += v.y; msg.z += v.z; msg.w += v.w;
            }
            float4 res;
            res.x = e4.x * (1.f - msg.x * inv);
            res.y = e4.y * (1.f - msg.y * inv);
            res.z = e4.z * (1.f - msg.z * inv);
            res.w = e4.w * (1.f - msg.w * inv);
            *((float4*)(out + (size_t)node * EMB_D) + lane) = res;
        }
    }
}

extern "C" void kernel_launch(void* const* d_in, const int* in_sizes, int n_in,
                              void* d_out, int out_size) {
    const float* emb  = (const float*)d_in[0];
    const int* s2row  = (const int*)d_in[1];
    const int* s2col  = (const int*)d_in[2];
    const int* s3row  = (const int*)d_in[3];
    const int* s3col  = (const int*)d_in[4];
    const int* ls     = (const int*)d_in[5];
    const int* rc     = (const int*)d_in[6];
    const int* lc     = (const int*)d_in[7];
    const int* rs     = (const int*)d_in[8];

    const int E2    = in_sizes[1];
    const int E3    = in_sizes[3];
    const int n_ent = in_sizes[5];
    const int n_typ = in_sizes[6];

    const int degGuess2 = (n_typ > 0) ? (E2 / n_typ) : 1;
    const int degGuess3 = (n_ent > 0) ? (E3 / n_ent) : 1;

    float* out = (float*)d_out;

    // Stage A: update type rows into out.
    k_type_update<<<n_typ, 512>>>(emb, s2row, s2col, E2, degGuess2, ls, rc,
                                  (float)n_ent, out);

    // Stage B: 64-node tiles.
    const int blocks = (n_ent + TILE - 1) / TILE;
    k_entity_tiled<<<blocks, 256>>>(emb, s3row, s3col, E3, degGuess3,
                                    lc, rs, n_ent, (float)n_typ, out);
}